// round 2
// baseline (speedup 1.0000x reference)
#include <cuda_runtime.h>
#include <math.h>

// Problem constants (fixed by the benchmark's setup_inputs)
#define C_CLASSES 16
#define D_DIM     256
#define N_MAX     32768
#define N_TILES   10          // upper-triangle 64x64 tiles of a 256x256 gram
#define LAM   25.0f
#define MU    25.0f
#define NU     1.0f
#define ALPHA 50.0f
#define EPS_V  1e-4f

// ---------------- scratch (device globals; no allocation allowed) ----------
__device__ int   g_counts[C_CLASSES];
__device__ int   g_offsets[C_CLASSES];
__device__ int   g_cursor[C_CLASSES];
__device__ int   g_idx[N_MAX];
__device__ float g_mean[2 * C_CLASSES * D_DIM];   // [view][class][d]
__device__ float g_var [2 * C_CLASSES * D_DIM];
__device__ float g_inv_partial[256];
__device__ float g_cov_partial[2 * C_CLASSES * N_TILES];

// ---------------- helpers ---------------------------------------------------
__device__ __forceinline__ float block_reduce_256(float v, float* red) {
    int tid = threadIdx.x;
    red[tid] = v;
    __syncthreads();
    #pragma unroll
    for (int s = 128; s > 0; s >>= 1) {
        if (tid < s) red[tid] += red[tid + s];
        __syncthreads();
    }
    float r = red[0];
    __syncthreads();
    return r;
}

// ---------------- K0: zero atomic accumulators ------------------------------
__global__ void k0_zero() {
    int t = threadIdx.x;
    if (t < C_CLASSES) g_counts[t] = 0;
}

// ---------------- K1: class histogram + invariance partial sums -------------
__global__ void k1_hist_inv(const float* __restrict__ za,
                            const float* __restrict__ zb,
                            const int* __restrict__ labels, int N) {
    int tid = threadIdx.x;
    int gid = blockIdx.x * 256 + tid;
    int stride = gridDim.x * 256;

    for (int r = gid; r < N; r += stride)
        atomicAdd(&g_counts[labels[r]], 1);

    const float4* a4 = (const float4*)za;
    const float4* b4 = (const float4*)zb;
    long total4 = (long)N * (D_DIM / 4);
    float s = 0.f;
    for (long e = gid; e < total4; e += stride) {
        float4 a = a4[e], b = b4[e];
        float dx = a.x - b.x, dy = a.y - b.y, dz = a.z - b.z, dw = a.w - b.w;
        s += dx * dx + dy * dy + dz * dz + dw * dw;
    }
    __shared__ float red[256];
    s = block_reduce_256(s, red);
    if (tid == 0) g_inv_partial[blockIdx.x] = s;
}

// ---------------- K2: prefix over 16 class counts ---------------------------
__global__ void k2_prefix() {
    if (threadIdx.x == 0) {
        int o = 0;
        for (int c = 0; c < C_CLASSES; c++) {
            g_offsets[c] = o;
            g_cursor[c]  = o;
            o += g_counts[c];
        }
    }
}

// ---------------- K3: scatter rows into class-sorted index list -------------
__global__ void k3_scatter(const int* __restrict__ labels, int N) {
    int t = blockIdx.x * 256 + threadIdx.x;
    if (t < N) {
        int pos = atomicAdd(&g_cursor[labels[t]], 1);
        g_idx[pos] = t;
    }
}

// ---------------- K4: per-class mean / unbiased var -------------------------
__global__ void k4_stats(const float* __restrict__ za,
                         const float* __restrict__ zb) {
    int c = blockIdx.x;
    int v = blockIdx.y;
    const float* x = v ? zb : za;
    int n    = g_counts[c];
    int base = g_offsets[c];
    int d    = threadIdx.x;

    float s = 0.f, q = 0.f;
    int i = 0;
    for (; i + 4 <= n; i += 4) {
        int r0 = g_idx[base + i + 0];
        int r1 = g_idx[base + i + 1];
        int r2 = g_idx[base + i + 2];
        int r3 = g_idx[base + i + 3];
        float v0 = x[r0 * D_DIM + d];
        float v1 = x[r1 * D_DIM + d];
        float v2 = x[r2 * D_DIM + d];
        float v3 = x[r3 * D_DIM + d];
        s += v0 + v1 + v2 + v3;
        q += v0 * v0 + v1 * v1 + v2 * v2 + v3 * v3;
    }
    for (; i < n; i++) {
        float vv = x[g_idx[base + i] * D_DIM + d];
        s += vv;
        q += vv * vv;
    }
    float fn   = (float)n;
    float mean = s / fn;
    int o = (v * C_CLASSES + c) * D_DIM + d;
    g_mean[o] = mean;
    g_var[o]  = (q - fn * mean * mean) / (fn - 1.f);
}

// ---------------- K5: per-class gram tiles -> covariance-loss partials ------
// Block = (tile, class, view). 64x64 tile, 256 threads, 4x4 micro-tile,
// K-batch = 16 rows. Only upper-triangle tiles; off-diag tiles weighted 2x.
__constant__ int c_ti[N_TILES] = {0,0,0,0,1,1,1,2,2,3};
__constant__ int c_tj[N_TILES] = {0,1,2,3,1,2,3,2,3,3};

__global__ void __launch_bounds__(256) k5_gram(const float* __restrict__ za,
                                               const float* __restrict__ zb) {
    int t = blockIdx.x;          // tile id 0..9
    int c = blockIdx.y;          // class
    int v = blockIdx.z;          // view
    const float* __restrict__ x = v ? zb : za;
    int ti = c_ti[t], tj = c_tj[t];

    __shared__ float As[16][64];
    __shared__ float Bs[16][64];

    int n    = g_counts[c];
    int base = g_offsets[c];
    int tid  = threadIdx.x;
    int ty   = tid >> 4;         // 0..15
    int tx   = tid & 15;         // 0..15

    float acc[4][4] = {};

    for (int k0 = 0; k0 < n; k0 += 16) {
        __syncthreads();   // previous compute done before overwrite
        // 512 float4 loads: each thread does 2 tasks
        #pragma unroll
        for (int task = tid; task < 512; task += 256) {
            int arr = task >> 8;          // 0:A 1:B
            int w   = task & 255;
            int kr  = w >> 4;             // 0..15
            int f4  = w & 15;             // 0..15
            int kk  = k0 + kr;
            float4 val = make_float4(0.f, 0.f, 0.f, 0.f);
            if (kk < n) {
                int r   = g_idx[base + kk];       // broadcast across 16 lanes
                int col = (arr ? tj : ti) * 64 + f4 * 4;
                val = *(const float4*)&x[r * D_DIM + col];
            }
            float* dst = arr ? &Bs[kr][f4 * 4] : &As[kr][f4 * 4];
            *(float4*)dst = val;
        }
        __syncthreads();
        #pragma unroll
        for (int k = 0; k < 16; k++) {
            float4 av = *(const float4*)&As[k][ty * 4];
            float4 bv = *(const float4*)&Bs[k][tx * 4];
            acc[0][0] += av.x * bv.x; acc[0][1] += av.x * bv.y;
            acc[0][2] += av.x * bv.z; acc[0][3] += av.x * bv.w;
            acc[1][0] += av.y * bv.x; acc[1][1] += av.y * bv.y;
            acc[1][2] += av.y * bv.z; acc[1][3] += av.y * bv.w;
            acc[2][0] += av.z * bv.x; acc[2][1] += av.z * bv.y;
            acc[2][2] += av.z * bv.z; acc[2][3] += av.z * bv.w;
            acc[3][0] += av.w * bv.x; acc[3][1] += av.w * bv.y;
            acc[3][2] += av.w * bv.z; acc[3][3] += av.w * bv.w;
        }
    }

    // cov correction + squared off-diagonal contribution
    const float* mrow = &g_mean[(v * C_CLASSES + c) * D_DIM];
    float mi[4], mj[4];
    #pragma unroll
    for (int u = 0; u < 4; u++) {
        mi[u] = mrow[ti * 64 + ty * 4 + u];
        mj[u] = mrow[tj * 64 + tx * 4 + u];
    }
    float fn = (float)n;
    float inv_nm1 = 1.f / (fn - 1.f);
    float wgt_tile = (ti == tj) ? 1.f : 2.f;
    float contrib = 0.f;
    #pragma unroll
    for (int u = 0; u < 4; u++) {
        #pragma unroll
        for (int w = 0; w < 4; w++) {
            float cov = (acc[u][w] - fn * mi[u] * mj[w]) * inv_nm1;
            int gi = ti * 64 + ty * 4 + u;
            int gj = tj * 64 + tx * 4 + w;
            float wgt = (gi == gj) ? 0.f : wgt_tile;
            contrib += wgt * cov * cov;
        }
    }
    __shared__ float red[256];
    contrib = block_reduce_256(contrib, red);
    if (tid == 0)
        g_cov_partial[(v * C_CLASSES + c) * N_TILES + t] = contrib;
}

// ---------------- K6: finalize all terms ------------------------------------
__global__ void k6_final(float* __restrict__ out, int N) {
    __shared__ float m[C_CLASSES * D_DIM];   // 16 KB combined class means
    __shared__ float red[256];
    int tid = threadIdx.x;

    for (int e = tid; e < C_CLASSES * D_DIM; e += 256)
        m[e] = 0.5f * (g_mean[e] + g_mean[C_CLASSES * D_DIM + e]);

    // invariance
    float inv_sum = block_reduce_256(g_inv_partial[tid], red);

    // variance
    float vsum = 0.f;
    for (int e = tid; e < 2 * C_CLASSES * D_DIM; e += 256) {
        float vv = g_var[e];
        vsum += fmaxf(0.f, 1.f - sqrtf(vv + EPS_V));
    }
    vsum = block_reduce_256(vsum, red);

    // covariance
    float csum = 0.f;
    for (int e = tid; e < 2 * C_CLASSES * N_TILES; e += 256)
        csum += g_cov_partial[e];
    csum = block_reduce_256(csum, red);

    // class-discriminative margin (120 pairs)
    float psum = 0.f;
    const int npairs = C_CLASSES * (C_CLASSES - 1) / 2;
    if (tid < npairs) {
        int i = 0, rem = tid;
        while (rem >= C_CLASSES - 1 - i) { rem -= C_CLASSES - 1 - i; i++; }
        int j = i + 1 + rem;
        float d2 = 0.f;
        for (int d = 0; d < D_DIM; d++) {
            float df = m[i * D_DIM + d] - m[j * D_DIM + d];
            d2 += df * df;
        }
        float dist = sqrtf(d2);
        float rr = fmaxf(0.f, ALPHA - dist);
        psum = rr * rr;
    }
    psum = block_reduce_256(psum, red);

    if (tid == 0) {
        float inv_loss   = inv_sum / ((float)N * (float)D_DIM);
        float var_loss   = vsum * 0.5f / ((float)C_CLASSES * (float)D_DIM);
        float cov_loss   = csum * 0.5f / ((float)C_CLASSES * (float)D_DIM);
        float class_loss = psum / (float)npairs;
        out[0] = LAM * inv_loss + MU * var_loss + NU * cov_loss + ALPHA * class_loss;
    }
}

// ---------------- launch -----------------------------------------------------
extern "C" void kernel_launch(void* const* d_in, const int* in_sizes, int n_in,
                              void* d_out, int out_size) {
    const float* za     = (const float*)d_in[0];
    const float* zb     = (const float*)d_in[1];
    const int*   labels = (const int*)d_in[2];
    int N = in_sizes[2];   // labels element count

    k0_zero<<<1, 32>>>();
    k1_hist_inv<<<256, 256>>>(za, zb, labels, N);
    k2_prefix<<<1, 32>>>();
    k3_scatter<<<(N + 255) / 256, 256>>>(labels, N);
    k4_stats<<<dim3(C_CLASSES, 2), 256>>>(za, zb);
    k5_gram<<<dim3(N_TILES, C_CLASSES, 2), 256>>>(za, zb);
    k6_final<<<1, 256>>>((float*)d_out, N);
}

// round 3
// speedup vs baseline: 2.5178x; 2.5178x over previous
#include <cuda_runtime.h>
#include <cuda_bf16.h>
#include <math.h>

// Problem constants (fixed by the benchmark's setup_inputs)
#define C_CLASSES 16
#define D_DIM     256
#define N_MAX     32768
#define N_TILES   10          // upper-triangle 64x64 tiles of a 256x256 gram
#define LAM   25.0f
#define MU    25.0f
#define NU     1.0f
#define ALPHA 50.0f
#define EPS_V  1e-4f

// ---------------- scratch (device globals; no allocation allowed) ----------
__device__ int   g_counts[C_CLASSES];
__device__ int   g_offsets[C_CLASSES];
__device__ int   g_cursor[C_CLASSES];
__device__ int   g_idx[N_MAX];
__device__ float g_s[2 * C_CLASSES * D_DIM];
__device__ float g_q[2 * C_CLASSES * D_DIM];
__device__ float g_mean[2 * C_CLASSES * D_DIM];   // [view][class][d]
__device__ float g_var [2 * C_CLASSES * D_DIM];
__device__ float g_inv_partial[128];
__device__ float g_cov_partial[2 * C_CLASSES * N_TILES];
__device__ __nv_bfloat16 g_a16[N_MAX * D_DIM];
__device__ __nv_bfloat16 g_b16[N_MAX * D_DIM];

// ---------------- helpers ---------------------------------------------------
__device__ __forceinline__ float block_reduce_256(float v, float* red) {
    int tid = threadIdx.x;
    red[tid] = v;
    __syncthreads();
    #pragma unroll
    for (int s = 128; s > 0; s >>= 1) {
        if (tid < s) red[tid] += red[tid + s];
        __syncthreads();
    }
    float r = red[0];
    __syncthreads();
    return r;
}

__device__ __forceinline__ void ldsm4t(unsigned& r0, unsigned& r1,
                                       unsigned& r2, unsigned& r3,
                                       unsigned addr) {
    asm volatile("ldmatrix.sync.aligned.m8n8.x4.trans.shared.b16 {%0,%1,%2,%3}, [%4];\n"
                 : "=r"(r0), "=r"(r1), "=r"(r2), "=r"(r3) : "r"(addr));
}

__device__ __forceinline__ void mma16816(float* c, unsigned a0, unsigned a1,
                                         unsigned a2, unsigned a3,
                                         unsigned b0, unsigned b1) {
    asm volatile("mma.sync.aligned.m16n8k16.row.col.f32.bf16.bf16.f32 "
                 "{%0,%1,%2,%3}, {%4,%5,%6,%7}, {%8,%9}, {%0,%1,%2,%3};\n"
                 : "+f"(c[0]), "+f"(c[1]), "+f"(c[2]), "+f"(c[3])
                 : "r"(a0), "r"(a1), "r"(a2), "r"(a3), "r"(b0), "r"(b1));
}

// ---------------- K0: zero accumulators -------------------------------------
__global__ void k0_zero() {
    int gid = blockIdx.x * 256 + threadIdx.x;   // grid 64 -> 16384 threads
    if (gid < C_CLASSES) g_counts[gid] = 0;
    if (gid < 2 * C_CLASSES * D_DIM) { g_s[gid] = 0.f; g_q[gid] = 0.f; }
}

// ---------------- K1: histogram + invariance + bf16 conversion --------------
__global__ void k1_inv_hist_cvt(const float* __restrict__ za,
                                const float* __restrict__ zb,
                                const int* __restrict__ labels, int N) {
    __shared__ int h[C_CLASSES];
    __shared__ float red[256];
    int tid = threadIdx.x;
    int gid = blockIdx.x * 256 + tid;
    if (tid < C_CLASSES) h[tid] = 0;
    __syncthreads();

    if (gid < N) atomicAdd(&h[labels[gid]], 1);

    const float4* a4 = (const float4*)za;
    const float4* b4 = (const float4*)zb;
    __nv_bfloat162* a16 = (__nv_bfloat162*)g_a16;
    __nv_bfloat162* b16 = (__nv_bfloat162*)g_b16;
    long total4 = (long)N * (D_DIM / 4);
    long stride = (long)gridDim.x * 256;
    float s = 0.f;
    for (long e = gid; e < total4; e += stride) {
        float4 a = a4[e], b = b4[e];
        float dx = a.x - b.x, dy = a.y - b.y, dz = a.z - b.z, dw = a.w - b.w;
        s += dx * dx + dy * dy + dz * dz + dw * dw;
        a16[2 * e]     = __floats2bfloat162_rn(a.x, a.y);
        a16[2 * e + 1] = __floats2bfloat162_rn(a.z, a.w);
        b16[2 * e]     = __floats2bfloat162_rn(b.x, b.y);
        b16[2 * e + 1] = __floats2bfloat162_rn(b.z, b.w);
    }
    __syncthreads();
    if (tid < C_CLASSES && h[tid] > 0) atomicAdd(&g_counts[tid], h[tid]);
    s = block_reduce_256(s, red);
    if (tid == 0) g_inv_partial[blockIdx.x] = s;
}

// ---------------- K2: prefix over 16 class counts ---------------------------
__global__ void k2_prefix() {
    if (threadIdx.x == 0) {
        int o = 0;
        for (int c = 0; c < C_CLASSES; c++) {
            g_offsets[c] = o;
            g_cursor[c]  = o;
            o += g_counts[c];
        }
    }
}

// ---------------- K3: scatter with smem-aggregated cursors ------------------
__global__ void k3_scatter(const int* __restrict__ labels, int N) {
    __shared__ int cnt[C_CLASSES];
    __shared__ int basev[C_CLASSES];
    int tid = threadIdx.x;
    int gid = blockIdx.x * 256 + tid;
    if (tid < C_CLASSES) cnt[tid] = 0;
    __syncthreads();
    int lab = -1, my = 0;
    if (gid < N) {
        lab = labels[gid];
        my = atomicAdd(&cnt[lab], 1);
    }
    __syncthreads();
    if (tid < C_CLASSES && cnt[tid] > 0)
        basev[tid] = atomicAdd(&g_cursor[tid], cnt[tid]);
    __syncthreads();
    if (gid < N)
        g_idx[basev[lab] + my] = gid;
}

// ---------------- K4: per-class partial sums (fp32) -------------------------
__global__ void k4_stats(const float* __restrict__ za,
                         const float* __restrict__ zb) {
    int c = blockIdx.x, v = blockIdx.y, ch = blockIdx.z;
    const float* __restrict__ x = v ? zb : za;
    int n    = g_counts[c];
    int base = g_offsets[c];
    int per  = (n + 7) >> 3;
    int lo = ch * per;
    int hi = min(n, lo + per);
    int d = threadIdx.x;
    float s = 0.f, q = 0.f;
    for (int i = lo; i < hi; i++) {
        float vv = x[g_idx[base + i] * D_DIM + d];
        s += vv;
        q += vv * vv;
    }
    int o = (v * C_CLASSES + c) * D_DIM + d;
    atomicAdd(&g_s[o], s);
    atomicAdd(&g_q[o], q);
}

// ---------------- K4b: finalize mean/var ------------------------------------
__global__ void k4b_meanvar() {
    int o = blockIdx.x * 256 + threadIdx.x;   // grid 32 -> 8192
    int c = (o >> 8) & (C_CLASSES - 1);
    float fn = (float)g_counts[c];
    float m = g_s[o] / fn;
    g_mean[o] = m;
    g_var[o]  = (g_q[o] - fn * m * m) / (fn - 1.f);
}

// ---------------- K5: bf16 tensor-core gram -> covariance partials ----------
// Block = (tile 0..9, class, view). 64x64 tile, 8 warps, mma.m16n8k16 bf16.
// SMEM tiles stored [k][dim] (natural layout); ldmatrix .trans supplies frags.
__constant__ int c_ti[N_TILES] = {0,0,0,0,1,1,1,2,2,3};
__constant__ int c_tj[N_TILES] = {0,1,2,3,1,2,3,2,3,3};

__global__ void __launch_bounds__(256) k5_gram() {
    int t = blockIdx.x;
    int c = blockIdx.y;
    int v = blockIdx.z;
    const __nv_bfloat16* __restrict__ x = v ? g_b16 : g_a16;
    int ti = c_ti[t], tj = c_tj[t];

    __shared__ __nv_bfloat16 As[32][72];   // k-chunk 32 x 64 dims (+8 pad)
    __shared__ __nv_bfloat16 Bs[32][72];
    __shared__ float red[256];

    int n    = g_counts[c];
    int base = g_offsets[c];
    int tid  = threadIdx.x;
    int lane = tid & 31;
    int warp = tid >> 5;

    int m0 = (warp >> 1) * 16;     // warp's m-block within 64
    int nh = (warp & 1) * 32;      // warp's n-half within 64

    unsigned aBase = (unsigned)__cvta_generic_to_shared(&As[0][0]);
    unsigned bBase = (unsigned)__cvta_generic_to_shared(&Bs[0][0]);
    // A frag addresses: matrices (m0..7,k0..7),(m8..15,k0..7),(m0..7,k8..15),(m8..15,k8..15)
    int a_row = (lane & 7) + ((lane >> 4) & 1) * 8;          // k within 16
    int a_col = m0 + ((lane >> 3) & 1) * 8;                  // m
    unsigned aAddr = aBase + (unsigned)(a_row * 72 + a_col) * 2u;
    // B frag addresses (x4 gives b0,b1 for two n-tiles): lanes0-7 (k0,n0),
    // 8-15 (k8,n0), 16-23 (k0,n0+8), 24-31 (k8,n0+8)
    int b_row = (lane & 7) + ((lane >> 3) & 1) * 8;          // k within 16
    int b_col = nh + ((lane >> 4) & 1) * 8;                  // n
    unsigned bAddr0 = bBase + (unsigned)(b_row * 72 + b_col) * 2u;
    unsigned bAddr1 = bAddr0 + 16u * 2u;                     // n-tiles +16

    // staging: thread loads one 16B segment of one row for A and B strips
    int kr  = tid >> 3;    // 0..31 (k row in chunk)
    int seg = tid & 7;     // 0..7  (16B segment within 64-dim strip)

    float acc[4][4] = {};  // [n-tile 0..3][c0..c3]

    for (int k0 = 0; k0 < n; k0 += 32) {
        __syncthreads();
        int kk = k0 + kr;
        int4 va = make_int4(0, 0, 0, 0), vb = va;
        if (kk < n) {
            int r = g_idx[base + kk];
            const int4* rowp = (const int4*)&x[r * D_DIM];
            va = rowp[ti * 8 + seg];
            vb = rowp[tj * 8 + seg];
        }
        *(int4*)&As[kr][seg * 8] = va;
        *(int4*)&Bs[kr][seg * 8] = vb;
        __syncthreads();
        #pragma unroll
        for (int ks = 0; ks < 32; ks += 16) {
            unsigned off = (unsigned)(ks * 72) * 2u;
            unsigned a0, a1, a2, a3;
            unsigned p0, p1, p2, p3;   // n-tiles 0,1
            unsigned q0, q1, q2, q3;   // n-tiles 2,3
            ldsm4t(a0, a1, a2, a3, aAddr + off);
            ldsm4t(p0, p1, p2, p3, bAddr0 + off);
            ldsm4t(q0, q1, q2, q3, bAddr1 + off);
            mma16816(acc[0], a0, a1, a2, a3, p0, p1);
            mma16816(acc[1], a0, a1, a2, a3, p2, p3);
            mma16816(acc[2], a0, a1, a2, a3, q0, q1);
            mma16816(acc[3], a0, a1, a2, a3, q2, q3);
        }
    }

    // cov correction + squared off-diagonal contribution
    int vc = v * C_CLASSES + c;
    const float* mrow = &g_mean[vc * D_DIM];
    int g  = lane >> 2;       // 0..7
    int tg = lane & 3;        // 0..3
    float fn = (float)n;
    float inv_nm1 = 1.f / (fn - 1.f);
    float wgt_tile = (ti == tj) ? 1.f : 2.f;
    float mi0 = mrow[ti * 64 + m0 + g];
    float mi1 = mrow[ti * 64 + m0 + g + 8];
    int gi0 = ti * 64 + m0 + g;
    int gi1 = gi0 + 8;
    float contrib = 0.f;
    #pragma unroll
    for (int nt = 0; nt < 4; nt++) {
        int n0 = nh + nt * 8;
        int gj0 = tj * 64 + n0 + 2 * tg;
        float mj0 = mrow[tj * 64 + n0 + 2 * tg];
        float mj1 = mrow[tj * 64 + n0 + 2 * tg + 1];
        float cv;
        cv = (acc[nt][0] - fn * mi0 * mj0) * inv_nm1;
        contrib += ((gi0 == gj0)     ? 0.f : wgt_tile) * cv * cv;
        cv = (acc[nt][1] - fn * mi0 * mj1) * inv_nm1;
        contrib += ((gi0 == gj0 + 1) ? 0.f : wgt_tile) * cv * cv;
        cv = (acc[nt][2] - fn * mi1 * mj0) * inv_nm1;
        contrib += ((gi1 == gj0)     ? 0.f : wgt_tile) * cv * cv;
        cv = (acc[nt][3] - fn * mi1 * mj1) * inv_nm1;
        contrib += ((gi1 == gj0 + 1) ? 0.f : wgt_tile) * cv * cv;
    }
    contrib = block_reduce_256(contrib, red);
    if (tid == 0)
        g_cov_partial[vc * N_TILES + t] = contrib;
}

// ---------------- K6: finalize all terms ------------------------------------
__global__ void k6_final(float* __restrict__ out, int N) {
    __shared__ float m[C_CLASSES * D_DIM];
    __shared__ float red[256];
    int tid = threadIdx.x;

    for (int e = tid; e < C_CLASSES * D_DIM; e += 256)
        m[e] = 0.5f * (g_mean[e] + g_mean[C_CLASSES * D_DIM + e]);

    // invariance (128 partials)
    float inv_sum = block_reduce_256(tid < 128 ? g_inv_partial[tid] : 0.f, red);

    // variance
    float vsum = 0.f;
    for (int e = tid; e < 2 * C_CLASSES * D_DIM; e += 256) {
        float vv = g_var[e];
        vsum += fmaxf(0.f, 1.f - sqrtf(vv + EPS_V));
    }
    vsum = block_reduce_256(vsum, red);

    // covariance
    float csum = 0.f;
    for (int e = tid; e < 2 * C_CLASSES * N_TILES; e += 256)
        csum += g_cov_partial[e];
    csum = block_reduce_256(csum, red);

    // class-discriminative margin (120 pairs)
    float psum = 0.f;
    const int npairs = C_CLASSES * (C_CLASSES - 1) / 2;
    if (tid < npairs) {
        int i = 0, rem = tid;
        while (rem >= C_CLASSES - 1 - i) { rem -= C_CLASSES - 1 - i; i++; }
        int j = i + 1 + rem;
        float d2 = 0.f;
        for (int d = 0; d < D_DIM; d++) {
            float df = m[i * D_DIM + d] - m[j * D_DIM + d];
            d2 += df * df;
        }
        float dist = sqrtf(d2);
        float rr = fmaxf(0.f, ALPHA - dist);
        psum = rr * rr;
    }
    psum = block_reduce_256(psum, red);

    if (tid == 0) {
        float inv_loss   = inv_sum / ((float)N * (float)D_DIM);
        float var_loss   = vsum * 0.5f / ((float)C_CLASSES * (float)D_DIM);
        float cov_loss   = csum * 0.5f / ((float)C_CLASSES * (float)D_DIM);
        float class_loss = psum / (float)npairs;
        out[0] = LAM * inv_loss + MU * var_loss + NU * cov_loss + ALPHA * class_loss;
    }
}

// ---------------- launch -----------------------------------------------------
extern "C" void kernel_launch(void* const* d_in, const int* in_sizes, int n_in,
                              void* d_out, int out_size) {
    const float* za     = (const float*)d_in[0];
    const float* zb     = (const float*)d_in[1];
    const int*   labels = (const int*)d_in[2];
    int N = in_sizes[2];   // labels element count

    k0_zero<<<64, 256>>>();
    k1_inv_hist_cvt<<<128, 256>>>(za, zb, labels, N);
    k2_prefix<<<1, 32>>>();
    k3_scatter<<<(N + 255) / 256, 256>>>(labels, N);
    k4_stats<<<dim3(C_CLASSES, 2, 8), 256>>>(za, zb);
    k4b_meanvar<<<32, 256>>>();
    k5_gram<<<dim3(N_TILES, C_CLASSES, 2), 256>>>();
    k6_final<<<1, 256>>>((float*)d_out, N);
}